// round 4
// baseline (speedup 1.0000x reference)
#include <cuda_runtime.h>
#include <cuda_fp16.h>
#include <math.h>

#define NN 50000
#define EE 1600000
#define H  64
#define CC 16
#define NBLK 196            // ceil(NN/256)

// ---- device scratch (allocation-free rule: static globals) ----
__device__ float   g_h[NN * H];         // linear output (fp32, for self-loop)
__device__ __half2 g_hh[NN * 32];       // linear output (fp16, for neighbor gather)
__device__ float   g_emb[NN * 3 * H];   // concat of the 3 normalized layer outputs
__device__ int     g_deg[NN];           // in-degree counter (re-zeroed by finalize)
__device__ float   g_dis[NN];           // rsqrt(deg + 1)
__device__ int     g_off[NN + 1];       // CSR row offsets
__device__ int     g_cur[NN];           // placement cursors
__device__ int     g_bsum[NBLK];        // per-block degree sums
__device__ int     g_bpre[NBLK];        // exclusive prefix of block sums
__device__ int     g_ecol[EE];          // CSR: source node per edge

// ---------------------------------------------------------------
// 1) in-degree histogram over target nodes
__global__ void k_hist(const int* __restrict__ rows) {
    int e = blockIdx.x * blockDim.x + threadIdx.x;
    if (e < EE) atomicAdd(&g_deg[rows[e]], 1);
}

// 2a) per-block sums of deg
__global__ void k_blocksum() {
    __shared__ int s[256];
    int i = blockIdx.x * 256 + threadIdx.x;
    int v = (i < NN) ? g_deg[i] : 0;
    s[threadIdx.x] = v;
    __syncthreads();
    for (int m = 128; m >= 1; m >>= 1) {
        if (threadIdx.x < m) s[threadIdx.x] += s[threadIdx.x + m];
        __syncthreads();
    }
    if (threadIdx.x == 0) g_bsum[blockIdx.x] = s[0];
}

// 2b) parallel exclusive scan of NBLK block sums (single block)
__global__ void k_scanbsum() {
    __shared__ int s[256];
    int t = threadIdx.x;
    int v = (t < NBLK) ? g_bsum[t] : 0;
    s[t] = v;
    __syncthreads();
    for (int m = 1; m < 256; m <<= 1) {
        int u = (t >= m) ? s[t - m] : 0;
        __syncthreads();
        s[t] += u;
        __syncthreads();
    }
    if (t < NBLK) g_bpre[t] = s[t] - v;
}

// 2c) finalize: in-block exclusive scan -> g_off, g_cur; dis; zero deg for replay
__global__ void k_finalize() {
    __shared__ int s[256];
    int i = blockIdx.x * 256 + threadIdx.x;
    int d = (i < NN) ? g_deg[i] : 0;
    s[threadIdx.x] = d;
    __syncthreads();
    for (int m = 1; m < 256; m <<= 1) {
        int t = (threadIdx.x >= m) ? s[threadIdx.x - m] : 0;
        __syncthreads();
        s[threadIdx.x] += t;
        __syncthreads();
    }
    if (i < NN) {
        int excl = g_bpre[blockIdx.x] + s[threadIdx.x] - d;
        g_off[i] = excl;
        g_cur[i] = excl;
        g_dis[i] = rsqrtf((float)(d + 1));
        g_deg[i] = 0;
    }
    if (i == 0) g_off[NN] = EE;
}

// 3) place edges into CSR slots (source col only, 4B/edge)
__global__ void k_place(const int* __restrict__ rows, const int* __restrict__ cols) {
    int e = blockIdx.x * blockDim.x + threadIdx.x;
    if (e >= EE) return;
    int r = rows[e];
    int c = cols[e];
    int pos = atomicAdd(&g_cur[r], 1);
    g_ecol[pos] = c;
}

// ---------------------------------------------------------------
// 4) h = in @ W, register-tiled: 64 nodes x 64 cols per block, 4x4 per thread.
//    Writes fp32 g_h and fp16 g_hh.
__global__ void k_matmul(const float* __restrict__ x, int src, const float* __restrict__ W) {
    __shared__ float Ws[64 * 64];
    __shared__ float xs[64][65];
    int tid = threadIdx.x;

    const float* in; int stride;
    if (src == 0)      { in = x;          stride = 64;  }
    else if (src == 1) { in = g_emb;      stride = 192; }
    else               { in = g_emb + 64; stride = 192; }

    int n0 = blockIdx.x * 64;
    for (int i = tid; i < 64 * 64; i += 256) Ws[i] = W[i];
    {
        int col = tid & 63;
        int rbase = (tid >> 6) * 16;
#pragma unroll
        for (int r = 0; r < 16; r++) {
            int row = rbase + r;
            int n = n0 + row;
            xs[row][col] = (n < NN) ? in[(size_t)n * stride + col] : 0.f;
        }
    }
    __syncthreads();

    int tj = (tid & 15) * 4;   // output col base
    int tn = (tid >> 4) * 4;   // node base (local)
    float acc[4][4];
#pragma unroll
    for (int i = 0; i < 4; i++)
#pragma unroll
        for (int j = 0; j < 4; j++) acc[i][j] = 0.f;

#pragma unroll 8
    for (int k = 0; k < 64; k++) {
        float4 w = *(const float4*)&Ws[k * 64 + tj];
        float x0 = xs[tn + 0][k];
        float x1 = xs[tn + 1][k];
        float x2 = xs[tn + 2][k];
        float x3 = xs[tn + 3][k];
        acc[0][0] = fmaf(x0, w.x, acc[0][0]); acc[0][1] = fmaf(x0, w.y, acc[0][1]);
        acc[0][2] = fmaf(x0, w.z, acc[0][2]); acc[0][3] = fmaf(x0, w.w, acc[0][3]);
        acc[1][0] = fmaf(x1, w.x, acc[1][0]); acc[1][1] = fmaf(x1, w.y, acc[1][1]);
        acc[1][2] = fmaf(x1, w.z, acc[1][2]); acc[1][3] = fmaf(x1, w.w, acc[1][3]);
        acc[2][0] = fmaf(x2, w.x, acc[2][0]); acc[2][1] = fmaf(x2, w.y, acc[2][1]);
        acc[2][2] = fmaf(x2, w.z, acc[2][2]); acc[2][3] = fmaf(x2, w.w, acc[2][3]);
        acc[3][0] = fmaf(x3, w.x, acc[3][0]); acc[3][1] = fmaf(x3, w.y, acc[3][1]);
        acc[3][2] = fmaf(x3, w.z, acc[3][2]); acc[3][3] = fmaf(x3, w.w, acc[3][3]);
    }

#pragma unroll
    for (int i = 0; i < 4; i++) {
        int n = n0 + tn + i;
        if (n < NN) {
            float4 o; o.x = acc[i][0]; o.y = acc[i][1]; o.z = acc[i][2]; o.w = acc[i][3];
            *(float4*)&g_h[n * 64 + tj] = o;
            __half2 h0 = __floats2half2_rn(acc[i][0], acc[i][1]);
            __half2 h1 = __floats2half2_rn(acc[i][2], acc[i][3]);
            __half2* dst = &g_hh[n * 32 + (tj >> 1)];
            dst[0] = h0;
            dst[1] = h1;
        }
    }
}

// ---------------------------------------------------------------
// 5) fused CSR aggregate (fp16 gather) + self-loop + bias + relu + L2norm + emb.
//    one warp per node, 2 features per lane.
__global__ void k_agg(const float* __restrict__ b, int off) {
    int node = (blockIdx.x * blockDim.x + threadIdx.x) >> 5;
    int lane = threadIdx.x & 31;
    if (node >= NN) return;

    int s = g_off[node];
    int e = g_off[node + 1];
    float dnode = g_dis[node];
    float accx = 0.f, accy = 0.f;

    int i = s;
    for (; i + 4 <= e; i += 4) {
        int c0 = g_ecol[i + 0];
        int c1 = g_ecol[i + 1];
        int c2 = g_ecol[i + 2];
        int c3 = g_ecol[i + 3];
        float n0 = dnode * g_dis[c0];
        float n1 = dnode * g_dis[c1];
        float n2 = dnode * g_dis[c2];
        float n3 = dnode * g_dis[c3];
        float2 v0 = __half22float2(g_hh[c0 * 32 + lane]);
        float2 v1 = __half22float2(g_hh[c1 * 32 + lane]);
        float2 v2 = __half22float2(g_hh[c2 * 32 + lane]);
        float2 v3 = __half22float2(g_hh[c3 * 32 + lane]);
        accx = fmaf(n0, v0.x, accx); accy = fmaf(n0, v0.y, accy);
        accx = fmaf(n1, v1.x, accx); accy = fmaf(n1, v1.y, accy);
        accx = fmaf(n2, v2.x, accx); accy = fmaf(n2, v2.y, accy);
        accx = fmaf(n3, v3.x, accx); accy = fmaf(n3, v3.y, accy);
    }
    for (; i < e; i++) {
        int c = g_ecol[i];
        float n = dnode * g_dis[c];
        float2 v = __half22float2(g_hh[c * 32 + lane]);
        accx = fmaf(n, v.x, accx); accy = fmaf(n, v.y, accy);
    }

    // self loop (fp32) + bias + relu
    float d2 = dnode * dnode;
    float2 hh = *(const float2*)(g_h + node * 64 + lane * 2);
    float bx = b[lane * 2], by = b[lane * 2 + 1];
    float vx = fmaxf(fmaf(d2, hh.x, accx) + bx, 0.f);
    float vy = fmaxf(fmaf(d2, hh.y, accy) + by, 0.f);

    // L2 normalize across warp
    float ss = vx * vx + vy * vy;
#pragma unroll
    for (int m = 16; m >= 1; m >>= 1)
        ss += __shfl_xor_sync(0xFFFFFFFFu, ss, m);
    float inv = 1.f / fmaxf(sqrtf(ss), 1e-12f);
    float2 o; o.x = vx * inv; o.y = vy * inv;
    *(float2*)(g_emb + (size_t)node * 192 + off + lane * 2) = o;
}

// ---------------------------------------------------------------
// 6) out = log_softmax(emb @ Wlin + blin).
//    Register-tiled: 64 nodes per block; thread = 1 class x 4 nodes.
__global__ void k_final(const float* __restrict__ Wlin, const float* __restrict__ blin,
                        float* __restrict__ out) {
    __shared__ float Ws[192 * 16];
    __shared__ float es[64][193];
    int tid = threadIdx.x;
    int n0 = blockIdx.x * 64;

    for (int i = tid; i < 192 * 16; i += 256) Ws[i] = Wlin[i];
    {
        int col = tid & 63;
        int rbase = (tid >> 6) * 16;
#pragma unroll
        for (int r = 0; r < 16; r++) {
            int row = rbase + r;
            int n = n0 + row;
            const float* src = g_emb + (size_t)n * 192;
#pragma unroll
            for (int p = 0; p < 3; p++)
                es[row][p * 64 + col] = (n < NN) ? src[p * 64 + col] : 0.f;
        }
    }
    __syncthreads();

    int c  = tid & 15;          // class
    int ng = tid >> 4;          // node group 0..15
    int nb = ng * 4;            // local node base
    float bias = blin[c];
    float acc[4] = {bias, bias, bias, bias};

#pragma unroll 8
    for (int k = 0; k < 192; k++) {
        float w = Ws[k * 16 + c];
        acc[0] = fmaf(es[nb + 0][k], w, acc[0]);
        acc[1] = fmaf(es[nb + 1][k], w, acc[1]);
        acc[2] = fmaf(es[nb + 2][k], w, acc[2]);
        acc[3] = fmaf(es[nb + 3][k], w, acc[3]);
    }

#pragma unroll
    for (int i = 0; i < 4; i++) {
        float a = acc[i];
        float m = a;
#pragma unroll
        for (int s = 8; s >= 1; s >>= 1)
            m = fmaxf(m, __shfl_xor_sync(0xFFFFFFFFu, m, s));
        float ex = __expf(a - m);
        float sum = ex;
#pragma unroll
        for (int s = 8; s >= 1; s >>= 1)
            sum += __shfl_xor_sync(0xFFFFFFFFu, sum, s);
        int n = n0 + nb + i;
        if (n < NN) out[n * 16 + c] = a - m - logf(sum);
    }
}

// ---------------------------------------------------------------
extern "C" void kernel_launch(void* const* d_in, const int* in_sizes, int n_in,
                              void* d_out, int out_size) {
    const float* x    = (const float*)d_in[0];
    const int*   ei   = (const int*)  d_in[1];
    const float* W1   = (const float*)d_in[2];
    const float* b1   = (const float*)d_in[3];
    const float* W2   = (const float*)d_in[4];
    const float* b2   = (const float*)d_in[5];
    const float* W3   = (const float*)d_in[6];
    const float* b3   = (const float*)d_in[7];
    const float* Wlin = (const float*)d_in[8];
    const float* blin = (const float*)d_in[9];
    float* out = (float*)d_out;

    const int* rows = ei;        // targets
    const int* cols = ei + EE;   // sources

    // ---- CSR build ----
    k_hist     <<<(EE + 255) / 256, 256>>>(rows);
    k_blocksum <<<NBLK, 256>>>();
    k_scanbsum <<<1, 256>>>();
    k_finalize <<<NBLK, 256>>>();
    k_place    <<<(EE + 255) / 256, 256>>>(rows, cols);

    // ---- 3 GCN layers ----
    const float* Wb[3][2] = { {W1, b1}, {W2, b2}, {W3, b3} };
    for (int L = 0; L < 3; L++) {
        k_matmul<<<(NN + 63) / 64, 256>>>(x, L, Wb[L][0]);
        k_agg   <<<(NN * 32 + 255) / 256, 256>>>(Wb[L][1], L * 64);
    }
    k_final<<<(NN + 63) / 64, 256>>>(Wlin, blin, out);
}

// round 6
// speedup vs baseline: 1.1893x; 1.1893x over previous
#include <cuda_runtime.h>
#include <cuda_fp16.h>
#include <math.h>

#define NN 50000
#define EE 1600000
#define H  64
#define CC 16
#define NBLK 196            // ceil(NN/256)

// ---- device scratch ----
__device__ __half2 g_hh[NN * 32];       // linear output (fp16), 128B per node row
__device__ float   g_emb[NN * 3 * H];   // concat of the 3 normalized layer outputs
__device__ int     g_deg[NN];           // in-degree counter (re-zeroed by finalize)
__device__ float   g_dis[NN];           // rsqrt(deg + 1)
__device__ int     g_off[NN + 1];       // CSR row offsets
__device__ int     g_cur[NN];           // placement cursors
__device__ int     g_bsum[NBLK];
__device__ int     g_bpre[NBLK];
__device__ int     g_ecol[EE];          // CSR: source node per edge

// ---------------------------------------------------------------
// 1) in-degree histogram, int4-vectorized
__global__ void k_hist(const int4* __restrict__ rows4) {
    int e = blockIdx.x * blockDim.x + threadIdx.x;
    if (e < EE / 4) {
        int4 r = rows4[e];
        atomicAdd(&g_deg[r.x], 1);
        atomicAdd(&g_deg[r.y], 1);
        atomicAdd(&g_deg[r.z], 1);
        atomicAdd(&g_deg[r.w], 1);
    }
}

// 2a) per-block sums of deg
__global__ void k_blocksum() {
    __shared__ int s[256];
    int i = blockIdx.x * 256 + threadIdx.x;
    int v = (i < NN) ? g_deg[i] : 0;
    s[threadIdx.x] = v;
    __syncthreads();
    for (int m = 128; m >= 1; m >>= 1) {
        if (threadIdx.x < m) s[threadIdx.x] += s[threadIdx.x + m];
        __syncthreads();
    }
    if (threadIdx.x == 0) g_bsum[blockIdx.x] = s[0];
}

// 2b) exclusive scan of NBLK block sums (single block)
__global__ void k_scanbsum() {
    __shared__ int s[256];
    int t = threadIdx.x;
    int v = (t < NBLK) ? g_bsum[t] : 0;
    s[t] = v;
    __syncthreads();
    for (int m = 1; m < 256; m <<= 1) {
        int u = (t >= m) ? s[t - m] : 0;
        __syncthreads();
        s[t] += u;
        __syncthreads();
    }
    if (t < NBLK) g_bpre[t] = s[t] - v;
}

// 2c) finalize: in-block exclusive scan -> g_off, g_cur; dis; zero deg for replay
__global__ void k_finalize() {
    __shared__ int s[256];
    int i = blockIdx.x * 256 + threadIdx.x;
    int d = (i < NN) ? g_deg[i] : 0;
    s[threadIdx.x] = d;
    __syncthreads();
    for (int m = 1; m < 256; m <<= 1) {
        int t = (threadIdx.x >= m) ? s[threadIdx.x - m] : 0;
        __syncthreads();
        s[threadIdx.x] += t;
        __syncthreads();
    }
    if (i < NN) {
        int excl = g_bpre[blockIdx.x] + s[threadIdx.x] - d;
        g_off[i] = excl;
        g_cur[i] = excl;
        g_dis[i] = rsqrtf((float)(d + 1));
        g_deg[i] = 0;
    }
    if (i == 0) g_off[NN] = EE;
}

// 3) place edges into CSR slots
__global__ void k_place(const int* __restrict__ rows, const int* __restrict__ cols) {
    int e = blockIdx.x * blockDim.x + threadIdx.x;
    if (e >= EE) return;
    int r = rows[e];
    int c = cols[e];
    int pos = atomicAdd(&g_cur[r], 1);
    g_ecol[pos] = c;
}

// ---------------------------------------------------------------
// 4) h = in @ W, register-tiled, fp16 output only.
__global__ void k_matmul(const float* __restrict__ x, int src, const float* __restrict__ W) {
    __shared__ float Ws[64 * 64];
    __shared__ float xs[64][65];
    int tid = threadIdx.x;

    const float* in; int stride;
    if (src == 0)      { in = x;          stride = 64;  }
    else if (src == 1) { in = g_emb;      stride = 192; }
    else               { in = g_emb + 64; stride = 192; }

    int n0 = blockIdx.x * 64;
    for (int i = tid; i < 64 * 64; i += 256) Ws[i] = W[i];
    {
        int col = tid & 63;
        int rbase = (tid >> 6) * 16;
#pragma unroll
        for (int r = 0; r < 16; r++) {
            int row = rbase + r;
            int n = n0 + row;
            xs[row][col] = (n < NN) ? in[(size_t)n * stride + col] : 0.f;
        }
    }
    __syncthreads();

    int tj = (tid & 15) * 4;
    int tn = (tid >> 4) * 4;
    float acc[4][4];
#pragma unroll
    for (int i = 0; i < 4; i++)
#pragma unroll
        for (int j = 0; j < 4; j++) acc[i][j] = 0.f;

#pragma unroll 8
    for (int k = 0; k < 64; k++) {
        float4 w = *(const float4*)&Ws[k * 64 + tj];
        float x0 = xs[tn + 0][k];
        float x1 = xs[tn + 1][k];
        float x2 = xs[tn + 2][k];
        float x3 = xs[tn + 3][k];
        acc[0][0] = fmaf(x0, w.x, acc[0][0]); acc[0][1] = fmaf(x0, w.y, acc[0][1]);
        acc[0][2] = fmaf(x0, w.z, acc[0][2]); acc[0][3] = fmaf(x0, w.w, acc[0][3]);
        acc[1][0] = fmaf(x1, w.x, acc[1][0]); acc[1][1] = fmaf(x1, w.y, acc[1][1]);
        acc[1][2] = fmaf(x1, w.z, acc[1][2]); acc[1][3] = fmaf(x1, w.w, acc[1][3]);
        acc[2][0] = fmaf(x2, w.x, acc[2][0]); acc[2][1] = fmaf(x2, w.y, acc[2][1]);
        acc[2][2] = fmaf(x2, w.z, acc[2][2]); acc[2][3] = fmaf(x2, w.w, acc[2][3]);
        acc[3][0] = fmaf(x3, w.x, acc[3][0]); acc[3][1] = fmaf(x3, w.y, acc[3][1]);
        acc[3][2] = fmaf(x3, w.z, acc[3][2]); acc[3][3] = fmaf(x3, w.w, acc[3][3]);
    }

#pragma unroll
    for (int i = 0; i < 4; i++) {
        int n = n0 + tn + i;
        if (n < NN) {
            __half2 h0 = __floats2half2_rn(acc[i][0], acc[i][1]);
            __half2 h1 = __floats2half2_rn(acc[i][2], acc[i][3]);
            uint2 o;
            o.x = *(unsigned int*)&h0;
            o.y = *(unsigned int*)&h1;
            *(uint2*)&g_hh[n * 32 + (tj >> 1)] = o;
        }
    }
}

// ---------------------------------------------------------------
// helper: acc += nm * half8(row segment)
__device__ __forceinline__ void acc8(float acc[8], uint4 r, float nm) {
    float2 f;
    f = __half22float2(*(__half2*)&r.x); acc[0] = fmaf(nm, f.x, acc[0]); acc[1] = fmaf(nm, f.y, acc[1]);
    f = __half22float2(*(__half2*)&r.y); acc[2] = fmaf(nm, f.x, acc[2]); acc[3] = fmaf(nm, f.y, acc[3]);
    f = __half22float2(*(__half2*)&r.z); acc[4] = fmaf(nm, f.x, acc[4]); acc[5] = fmaf(nm, f.y, acc[5]);
    f = __half22float2(*(__half2*)&r.w); acc[6] = fmaf(nm, f.x, acc[6]); acc[7] = fmaf(nm, f.y, acc[7]);
}

// 5) fused CSR aggregate + self-loop + bias + relu + L2norm + emb write.
//    4 nodes per warp, 8 lanes per node, uint4 (8 fp16 features) per lane.
__global__ void k_agg(const float* __restrict__ b, int off) {
    int w    = (blockIdx.x * blockDim.x + threadIdx.x) >> 5;
    int lane = threadIdx.x & 31;
    int g = lane >> 3;      // node group 0..3
    int t = lane & 7;       // lane within group
    int node = w * 4 + g;
    bool valid = node < NN;
    int nc = valid ? node : NN - 1;

    int s   = g_off[nc];
    int len = valid ? (g_off[nc + 1] - s) : 0;
    float dnode = g_dis[nc];

    const uint4* hhv = (const uint4*)g_hh;   // 8 x uint4 per node row

    float acc[8];
#pragma unroll
    for (int j = 0; j < 8; j++) acc[j] = 0.f;

    int i = 0;
    for (; i + 2 <= len; i += 2) {
        int c0 = g_ecol[s + i];
        int c1 = g_ecol[s + i + 1];
        float n0 = dnode * g_dis[c0];
        float n1 = dnode * g_dis[c1];
        uint4 r0 = hhv[c0 * 8 + t];
        uint4 r1 = hhv[c1 * 8 + t];
        acc8(acc, r0, n0);
        acc8(acc, r1, n1);
    }
    if (i < len) {
        int c = g_ecol[s + i];
        float nm = dnode * g_dis[c];
        uint4 r = hhv[c * 8 + t];
        acc8(acc, r, nm);
    }

    // self loop + bias + relu
    float d2 = dnode * dnode;
    uint4 sr = hhv[nc * 8 + t];
    float self[8];
    {
        float2 f;
        f = __half22float2(*(__half2*)&sr.x); self[0] = f.x; self[1] = f.y;
        f = __half22float2(*(__half2*)&sr.y); self[2] = f.x; self[3] = f.y;
        f = __half22float2(*(__half2*)&sr.z); self[4] = f.x; self[5] = f.y;
        f = __half22float2(*(__half2*)&sr.w); self[6] = f.x; self[7] = f.y;
    }
    float4 b0 = *(const float4*)(b + t * 8);
    float4 b1 = *(const float4*)(b + t * 8 + 4);
    float v[8];
    v[0] = fmaxf(fmaf(d2, self[0], acc[0]) + b0.x, 0.f);
    v[1] = fmaxf(fmaf(d2, self[1], acc[1]) + b0.y, 0.f);
    v[2] = fmaxf(fmaf(d2, self[2], acc[2]) + b0.z, 0.f);
    v[3] = fmaxf(fmaf(d2, self[3], acc[3]) + b0.w, 0.f);
    v[4] = fmaxf(fmaf(d2, self[4], acc[4]) + b1.x, 0.f);
    v[5] = fmaxf(fmaf(d2, self[5], acc[5]) + b1.y, 0.f);
    v[6] = fmaxf(fmaf(d2, self[6], acc[6]) + b1.z, 0.f);
    v[7] = fmaxf(fmaf(d2, self[7], acc[7]) + b1.w, 0.f);

    // L2 norm across the 8-lane group (xor 4,2,1 stays in-group)
    float ss = 0.f;
#pragma unroll
    for (int j = 0; j < 8; j++) ss = fmaf(v[j], v[j], ss);
#pragma unroll
    for (int m = 4; m >= 1; m >>= 1)
        ss += __shfl_xor_sync(0xFFFFFFFFu, ss, m);
    float inv = 1.f / fmaxf(sqrtf(ss), 1e-12f);

    if (valid) {
        float* dst = g_emb + (size_t)node * 192 + off + t * 8;
        float4 o0; o0.x = v[0] * inv; o0.y = v[1] * inv; o0.z = v[2] * inv; o0.w = v[3] * inv;
        float4 o1; o1.x = v[4] * inv; o1.y = v[5] * inv; o1.z = v[6] * inv; o1.w = v[7] * inv;
        *(float4*)dst = o0;
        *(float4*)(dst + 4) = o1;
    }
}

// ---------------------------------------------------------------
// 6) out = log_softmax(emb @ Wlin + blin). Register-tiled.
__global__ void k_final(const float* __restrict__ Wlin, const float* __restrict__ blin,
                        float* __restrict__ out) {
    __shared__ float Ws[192 * 16];
    __shared__ float es[64][193];
    int tid = threadIdx.x;
    int n0 = blockIdx.x * 64;

    for (int i = tid; i < 192 * 16; i += 256) Ws[i] = Wlin[i];
    {
        int col = tid & 63;
        int rbase = (tid >> 6) * 16;
#pragma unroll
        for (int r = 0; r < 16; r++) {
            int row = rbase + r;
            int n = n0 + row;
            const float* src = g_emb + (size_t)n * 192;
#pragma unroll
            for (int p = 0; p < 3; p++)
                es[row][p * 64 + col] = (n < NN) ? src[p * 64 + col] : 0.f;
        }
    }
    __syncthreads();

    int c  = tid & 15;
    int nb = (tid >> 4) * 4;
    float bias = blin[c];
    float acc[4] = {bias, bias, bias, bias};

#pragma unroll 8
    for (int k = 0; k < 192; k++) {
        float w = Ws[k * 16 + c];
        acc[0] = fmaf(es[nb + 0][k], w, acc[0]);
        acc[1] = fmaf(es[nb + 1][k], w, acc[1]);
        acc[2] = fmaf(es[nb + 2][k], w, acc[2]);
        acc[3] = fmaf(es[nb + 3][k], w, acc[3]);
    }

#pragma unroll
    for (int i = 0; i < 4; i++) {
        float a = acc[i];
        float m = a;
#pragma unroll
        for (int s = 8; s >= 1; s >>= 1)
            m = fmaxf(m, __shfl_xor_sync(0xFFFFFFFFu, m, s));
        float ex = __expf(a - m);
        float sum = ex;
#pragma unroll
        for (int s = 8; s >= 1; s >>= 1)
            sum += __shfl_xor_sync(0xFFFFFFFFu, sum, s);
        int n = n0 + nb + i;
        if (n < NN) out[n * 16 + c] = a - m - logf(sum);
    }
}

// ---------------------------------------------------------------
extern "C" void kernel_launch(void* const* d_in, const int* in_sizes, int n_in,
                              void* d_out, int out_size) {
    const float* x    = (const float*)d_in[0];
    const int*   ei   = (const int*)  d_in[1];
    const float* W1   = (const float*)d_in[2];
    const float* b1   = (const float*)d_in[3];
    const float* W2   = (const float*)d_in[4];
    const float* b2   = (const float*)d_in[5];
    const float* W3   = (const float*)d_in[6];
    const float* b3   = (const float*)d_in[7];
    const float* Wlin = (const float*)d_in[8];
    const float* blin = (const float*)d_in[9];
    float* out = (float*)d_out;

    const int* rows = ei;        // targets
    const int* cols = ei + EE;   // sources

    // ---- CSR build (matmul1 slotted at launch index 4 for ncu visibility) ----
    k_hist     <<<(EE / 4 + 255) / 256, 256>>>((const int4*)rows);
    k_blocksum <<<NBLK, 256>>>();
    k_scanbsum <<<1, 256>>>();
    k_matmul   <<<(NN + 63) / 64, 256>>>(x, 0, W1);     // layer-1 matmul (CSR-independent)
    k_finalize <<<NBLK, 256>>>();
    k_place    <<<(EE + 255) / 256, 256>>>(rows, cols);

    // ---- 3 GCN layers ----
    int aggBlocks = ((NN + 3) / 4 * 32 + 255) / 256;
    k_agg   <<<aggBlocks, 256>>>(b1, 0);
    k_matmul<<<(NN + 63) / 64, 256>>>(x, 1, W2);
    k_agg   <<<aggBlocks, 256>>>(b2, 64);
    k_matmul<<<(NN + 63) / 64, 256>>>(x, 2, W3);
    k_agg   <<<aggBlocks, 256>>>(b3, 128);

    k_final<<<(NN + 63) / 64, 256>>>(Wlin, blin, out);
}

// round 7
// speedup vs baseline: 1.2072x; 1.0150x over previous
#include <cuda_runtime.h>
#include <cuda_fp16.h>
#include <math.h>

#define NN 50000
#define EE 1600000
#define H  64
#define CC 16
#define NBLK 196            // ceil(NN/256)

// ---- device scratch ----
__device__ __half2 g_hh[NN * 32];       // linear output (fp16), 128B per node row
__device__ float   g_emb[NN * 3 * H];   // concat of the 3 normalized layer outputs
__device__ int     g_deg[NN];           // in-degree counter (re-zeroed by finalize)
__device__ float   g_dis[NN];           // rsqrt(deg + 1)
__device__ int     g_off[NN + 1];       // CSR row offsets
__device__ int     g_cur[NN];           // placement cursors
__device__ int     g_bsum[NBLK];
__device__ int     g_bpre[NBLK];
__device__ int     g_ecol[EE];          // CSR: source node per edge

// ---------------------------------------------------------------
// 1) in-degree histogram, int4-vectorized
__global__ void k_hist(const int4* __restrict__ rows4) {
    int e = blockIdx.x * blockDim.x + threadIdx.x;
    if (e < EE / 4) {
        int4 r = rows4[e];
        atomicAdd(&g_deg[r.x], 1);
        atomicAdd(&g_deg[r.y], 1);
        atomicAdd(&g_deg[r.z], 1);
        atomicAdd(&g_deg[r.w], 1);
    }
}

// 2a) per-block sums of deg
__global__ void k_blocksum() {
    __shared__ int s[256];
    int i = blockIdx.x * 256 + threadIdx.x;
    int v = (i < NN) ? g_deg[i] : 0;
    s[threadIdx.x] = v;
    __syncthreads();
    for (int m = 128; m >= 1; m >>= 1) {
        if (threadIdx.x < m) s[threadIdx.x] += s[threadIdx.x + m];
        __syncthreads();
    }
    if (threadIdx.x == 0) g_bsum[blockIdx.x] = s[0];
}

// 2b) exclusive scan of NBLK block sums (single block)
__global__ void k_scanbsum() {
    __shared__ int s[256];
    int t = threadIdx.x;
    int v = (t < NBLK) ? g_bsum[t] : 0;
    s[t] = v;
    __syncthreads();
    for (int m = 1; m < 256; m <<= 1) {
        int u = (t >= m) ? s[t - m] : 0;
        __syncthreads();
        s[t] += u;
        __syncthreads();
    }
    if (t < NBLK) g_bpre[t] = s[t] - v;
}

// 2c) finalize: in-block exclusive scan -> g_off, g_cur; dis; zero deg for replay
__global__ void k_finalize() {
    __shared__ int s[256];
    int i = blockIdx.x * 256 + threadIdx.x;
    int d = (i < NN) ? g_deg[i] : 0;
    s[threadIdx.x] = d;
    __syncthreads();
    for (int m = 1; m < 256; m <<= 1) {
        int t = (threadIdx.x >= m) ? s[threadIdx.x - m] : 0;
        __syncthreads();
        s[threadIdx.x] += t;
        __syncthreads();
    }
    if (i < NN) {
        int excl = g_bpre[blockIdx.x] + s[threadIdx.x] - d;
        g_off[i] = excl;
        g_cur[i] = excl;
        g_dis[i] = rsqrtf((float)(d + 1));
        g_deg[i] = 0;
    }
    if (i == 0) g_off[NN] = EE;
}

// 3) place edges into CSR slots
__global__ void k_place(const int* __restrict__ rows, const int* __restrict__ cols) {
    int e = blockIdx.x * blockDim.x + threadIdx.x;
    if (e >= EE) return;
    int r = rows[e];
    int c = cols[e];
    int pos = atomicAdd(&g_cur[r], 1);
    g_ecol[pos] = c;
}

// ---------------------------------------------------------------
// 4) h = in @ W, register-tiled 4 nodes x 8 cols per thread, fp16 output.
//    128 threads, 64 nodes per block.
__global__ void k_matmul(const float* __restrict__ x, int src, const float* __restrict__ W) {
    __shared__ float Ws[64 * 64];
    __shared__ float xs[64][65];
    int tid = threadIdx.x;   // 0..127

    const float* in; int stride;
    if (src == 0)      { in = x;          stride = 64;  }
    else if (src == 1) { in = g_emb;      stride = 192; }
    else               { in = g_emb + 64; stride = 192; }

    int n0 = blockIdx.x * 64;
    for (int i = tid; i < 64 * 64; i += 128) Ws[i] = W[i];
    {
        int col = tid & 63;
        int rb  = (tid >> 6) * 32;
#pragma unroll
        for (int r = 0; r < 32; r++) {
            int row = rb + r;
            int n = n0 + row;
            xs[row][col] = (n < NN) ? in[(size_t)n * stride + col] : 0.f;
        }
    }
    __syncthreads();

    int tj = (tid & 7) * 8;   // output col base (8 cols)
    int tn = (tid >> 3) * 4;  // node base (4 nodes)
    float acc[4][8];
#pragma unroll
    for (int i = 0; i < 4; i++)
#pragma unroll
        for (int j = 0; j < 8; j++) acc[i][j] = 0.f;

#pragma unroll 8
    for (int k = 0; k < 64; k++) {
        float4 wa = *(const float4*)&Ws[k * 64 + tj];
        float4 wb = *(const float4*)&Ws[k * 64 + tj + 4];
        float xv[4];
        xv[0] = xs[tn + 0][k];
        xv[1] = xs[tn + 1][k];
        xv[2] = xs[tn + 2][k];
        xv[3] = xs[tn + 3][k];
#pragma unroll
        for (int i = 0; i < 4; i++) {
            acc[i][0] = fmaf(xv[i], wa.x, acc[i][0]);
            acc[i][1] = fmaf(xv[i], wa.y, acc[i][1]);
            acc[i][2] = fmaf(xv[i], wa.z, acc[i][2]);
            acc[i][3] = fmaf(xv[i], wa.w, acc[i][3]);
            acc[i][4] = fmaf(xv[i], wb.x, acc[i][4]);
            acc[i][5] = fmaf(xv[i], wb.y, acc[i][5]);
            acc[i][6] = fmaf(xv[i], wb.z, acc[i][6]);
            acc[i][7] = fmaf(xv[i], wb.w, acc[i][7]);
        }
    }

#pragma unroll
    for (int i = 0; i < 4; i++) {
        int n = n0 + tn + i;
        if (n < NN) {
            __half2 h0 = __floats2half2_rn(acc[i][0], acc[i][1]);
            __half2 h1 = __floats2half2_rn(acc[i][2], acc[i][3]);
            __half2 h2 = __floats2half2_rn(acc[i][4], acc[i][5]);
            __half2 h3 = __floats2half2_rn(acc[i][6], acc[i][7]);
            uint4 o;
            o.x = *(unsigned int*)&h0;
            o.y = *(unsigned int*)&h1;
            o.z = *(unsigned int*)&h2;
            o.w = *(unsigned int*)&h3;
            ((uint4*)g_hh)[n * 8 + (tj >> 3)] = o;
        }
    }
}

// ---------------------------------------------------------------
// helper: acc += nm * half8(row segment)
__device__ __forceinline__ void acc8(float acc[8], uint4 r, float nm) {
    float2 f;
    f = __half22float2(*(__half2*)&r.x); acc[0] = fmaf(nm, f.x, acc[0]); acc[1] = fmaf(nm, f.y, acc[1]);
    f = __half22float2(*(__half2*)&r.y); acc[2] = fmaf(nm, f.x, acc[2]); acc[3] = fmaf(nm, f.y, acc[3]);
    f = __half22float2(*(__half2*)&r.z); acc[4] = fmaf(nm, f.x, acc[4]); acc[5] = fmaf(nm, f.y, acc[5]);
    f = __half22float2(*(__half2*)&r.w); acc[6] = fmaf(nm, f.x, acc[6]); acc[7] = fmaf(nm, f.y, acc[7]);
}

// 5) fused CSR aggregate + self-loop + bias + relu + L2norm + emb write.
//    4 nodes per warp, 8 lanes per node, uint4 (8 fp16 features) per lane.
__global__ void k_agg(const float* __restrict__ b, int off) {
    int w    = (blockIdx.x * blockDim.x + threadIdx.x) >> 5;
    int lane = threadIdx.x & 31;
    int g = lane >> 3;      // node group 0..3
    int t = lane & 7;       // lane within group
    int node = w * 4 + g;
    bool valid = node < NN;
    int nc = valid ? node : NN - 1;

    int s   = g_off[nc];
    int len = valid ? (g_off[nc + 1] - s) : 0;
    float dnode = g_dis[nc];

    const uint4* hhv = (const uint4*)g_hh;   // 8 x uint4 per node row

    float acc[8];
#pragma unroll
    for (int j = 0; j < 8; j++) acc[j] = 0.f;

    int i = 0;
    for (; i + 2 <= len; i += 2) {
        int c0 = g_ecol[s + i];
        int c1 = g_ecol[s + i + 1];
        float n0 = dnode * g_dis[c0];
        float n1 = dnode * g_dis[c1];
        uint4 r0 = hhv[c0 * 8 + t];
        uint4 r1 = hhv[c1 * 8 + t];
        acc8(acc, r0, n0);
        acc8(acc, r1, n1);
    }
    if (i < len) {
        int c = g_ecol[s + i];
        float nm = dnode * g_dis[c];
        uint4 r = hhv[c * 8 + t];
        acc8(acc, r, nm);
    }

    // self loop + bias + relu
    float d2 = dnode * dnode;
    uint4 sr = hhv[nc * 8 + t];
    float self[8];
    {
        float2 f;
        f = __half22float2(*(__half2*)&sr.x); self[0] = f.x; self[1] = f.y;
        f = __half22float2(*(__half2*)&sr.y); self[2] = f.x; self[3] = f.y;
        f = __half22float2(*(__half2*)&sr.z); self[4] = f.x; self[5] = f.y;
        f = __half22float2(*(__half2*)&sr.w); self[6] = f.x; self[7] = f.y;
    }
    float4 b0 = *(const float4*)(b + t * 8);
    float4 b1 = *(const float4*)(b + t * 8 + 4);
    float v[8];
    v[0] = fmaxf(fmaf(d2, self[0], acc[0]) + b0.x, 0.f);
    v[1] = fmaxf(fmaf(d2, self[1], acc[1]) + b0.y, 0.f);
    v[2] = fmaxf(fmaf(d2, self[2], acc[2]) + b0.z, 0.f);
    v[3] = fmaxf(fmaf(d2, self[3], acc[3]) + b0.w, 0.f);
    v[4] = fmaxf(fmaf(d2, self[4], acc[4]) + b1.x, 0.f);
    v[5] = fmaxf(fmaf(d2, self[5], acc[5]) + b1.y, 0.f);
    v[6] = fmaxf(fmaf(d2, self[6], acc[6]) + b1.z, 0.f);
    v[7] = fmaxf(fmaf(d2, self[7], acc[7]) + b1.w, 0.f);

    // L2 norm across the 8-lane group (xor 4,2,1 stays in-group)
    float ss = 0.f;
#pragma unroll
    for (int j = 0; j < 8; j++) ss = fmaf(v[j], v[j], ss);
#pragma unroll
    for (int m = 4; m >= 1; m >>= 1)
        ss += __shfl_xor_sync(0xFFFFFFFFu, ss, m);
    float inv = 1.f / fmaxf(sqrtf(ss), 1e-12f);

    if (valid) {
        float* dst = g_emb + (size_t)node * 192 + off + t * 8;
        float4 o0; o0.x = v[0] * inv; o0.y = v[1] * inv; o0.z = v[2] * inv; o0.w = v[3] * inv;
        float4 o1; o1.x = v[4] * inv; o1.y = v[5] * inv; o1.z = v[6] * inv; o1.w = v[7] * inv;
        *(float4*)dst = o0;
        *(float4*)(dst + 4) = o1;
    }
}

// ---------------------------------------------------------------
// 6) out = log_softmax(emb @ Wlin + blin). Register-tiled.
__global__ void k_final(const float* __restrict__ Wlin, const float* __restrict__ blin,
                        float* __restrict__ out) {
    __shared__ float Ws[192 * 16];
    __shared__ float es[64][193];
    int tid = threadIdx.x;
    int n0 = blockIdx.x * 64;

    for (int i = tid; i < 192 * 16; i += 256) Ws[i] = Wlin[i];
    {
        int col = tid & 63;
        int rbase = (tid >> 6) * 16;
#pragma unroll
        for (int r = 0; r < 16; r++) {
            int row = rbase + r;
            int n = n0 + row;
            const float* src = g_emb + (size_t)n * 192;
#pragma unroll
            for (int p = 0; p < 3; p++)
                es[row][p * 64 + col] = (n < NN) ? src[p * 64 + col] : 0.f;
        }
    }
    __syncthreads();

    int c  = tid & 15;
    int nb = (tid >> 4) * 4;
    float bias = blin[c];
    float acc[4] = {bias, bias, bias, bias};

#pragma unroll 8
    for (int k = 0; k < 192; k++) {
        float w = Ws[k * 16 + c];
        acc[0] = fmaf(es[nb + 0][k], w, acc[0]);
        acc[1] = fmaf(es[nb + 1][k], w, acc[1]);
        acc[2] = fmaf(es[nb + 2][k], w, acc[2]);
        acc[3] = fmaf(es[nb + 3][k], w, acc[3]);
    }

#pragma unroll
    for (int i = 0; i < 4; i++) {
        float a = acc[i];
        float m = a;
#pragma unroll
        for (int s = 8; s >= 1; s >>= 1)
            m = fmaxf(m, __shfl_xor_sync(0xFFFFFFFFu, m, s));
        float ex = __expf(a - m);
        float sum = ex;
#pragma unroll
        for (int s = 8; s >= 1; s >>= 1)
            sum += __shfl_xor_sync(0xFFFFFFFFu, sum, s);
        int n = n0 + nb + i;
        if (n < NN) out[n * 16 + c] = a - m - logf(sum);
    }
}

// ---------------------------------------------------------------
extern "C" void kernel_launch(void* const* d_in, const int* in_sizes, int n_in,
                              void* d_out, int out_size) {
    const float* x    = (const float*)d_in[0];
    const int*   ei   = (const int*)  d_in[1];
    const float* W1   = (const float*)d_in[2];
    const float* b1   = (const float*)d_in[3];
    const float* W2   = (const float*)d_in[4];
    const float* b2   = (const float*)d_in[5];
    const float* W3   = (const float*)d_in[6];
    const float* b3   = (const float*)d_in[7];
    const float* Wlin = (const float*)d_in[8];
    const float* blin = (const float*)d_in[9];
    float* out = (float*)d_out;

    const int* rows = ei;        // targets
    const int* cols = ei + EE;   // sources

    // lazily created side stream + events (host objects, no device memory)
    static cudaStream_t s2 = nullptr;
    static cudaEvent_t ev_fork = nullptr, ev_join = nullptr;
    if (!s2) {
        cudaStreamCreateWithFlags(&s2, cudaStreamNonBlocking);
        cudaEventCreateWithFlags(&ev_fork, cudaEventDisableTiming);
        cudaEventCreateWithFlags(&ev_join, cudaEventDisableTiming);
    }
    cudaStream_t s0 = 0;

    // ---- fork: matmul1 (depends only on x, W1) runs beside CSR build ----
    cudaEventRecord(ev_fork, s0);
    cudaStreamWaitEvent(s2, ev_fork, 0);
    k_matmul<<<(NN + 63) / 64, 128, 0, s2>>>(x, 0, W1);
    cudaEventRecord(ev_join, s2);

    // ---- CSR build on main stream ----
    k_hist     <<<(EE / 4 + 255) / 256, 256, 0, s0>>>((const int4*)rows);
    k_blocksum <<<NBLK, 256, 0, s0>>>();
    k_scanbsum <<<1, 256, 0, s0>>>();
    k_finalize <<<NBLK, 256, 0, s0>>>();
    k_place    <<<(EE + 255) / 256, 256, 0, s0>>>(rows, cols);

    // ---- join, then 3 GCN layers ----
    cudaStreamWaitEvent(s0, ev_join, 0);
    int aggBlocks = ((NN + 3) / 4 * 32 + 255) / 256;
    k_agg   <<<aggBlocks, 256, 0, s0>>>(b1, 0);
    k_matmul<<<(NN + 63) / 64, 128, 0, s0>>>(x, 1, W2);
    k_agg   <<<aggBlocks, 256, 0, s0>>>(b2, 64);
    k_matmul<<<(NN + 63) / 64, 128, 0, s0>>>(x, 2, W3);
    k_agg   <<<aggBlocks, 256, 0, s0>>>(b3, 128);

    k_final<<<(NN + 63) / 64, 256, 0, s0>>>(Wlin, blin, out);
}